// round 9
// baseline (speedup 1.0000x reference)
#include <cuda_runtime.h>
#include <cuda_bf16.h>
#include <math.h>

// Lowpass EMA scan: out[b,t,u] = (1-s[u])*x[b,t,u] + s[u]*prev
// Thread-per-chain (carry in register) + cp.async-staged input tiles.
// R9: 256 blocks x 64 threads so ALL 148 SMs participate (128-block
// version idled 20 SMs). Stage = 64t x 64u = 16KB; RING=6, 4 tiles in
// flight, R7 ordering (wait -> issue -> consume).

#define LP_B   16
#define LP_T   2048
#define LP_U   1024
#define TPB    64            // threads = chains per block
#define TT     64            // t per tile
#define NIT    (LP_T / TT)   // 32
#define RING   6
#define STAGE_FLOATS (TT * TPB)                 // 4096 floats = 16KB
#define SMEM_BYTES   (RING * STAGE_FLOATS * 4)  // 96KB

__device__ __forceinline__ void cp_async16(float* smem_dst, const float* gsrc) {
    unsigned sdst = (unsigned)__cvta_generic_to_shared(smem_dst);
    asm volatile("cp.async.cg.shared.global [%0], [%1], 16;\n"
                 :: "r"(sdst), "l"(gsrc));
}
__device__ __forceinline__ void cp_async_commit() {
    asm volatile("cp.async.commit_group;\n" ::: "memory");
}
template <int N>
__device__ __forceinline__ void cp_async_wait() {
    asm volatile("cp.async.wait_group %0;\n" :: "n"(N) : "memory");
}

__global__ void __launch_bounds__(TPB, 2)
lowpass_cpasync_kernel(const float* __restrict__ x,
                       const float* __restrict__ level_var,
                       const float* __restrict__ smoothing_var,
                       float* __restrict__ out)
{
    extern __shared__ float xs[];   // [RING][TT][TPB]

    const int tid = threadIdx.x;
    const int b   = blockIdx.x >> 4;           // 0..15
    const int u0  = (blockIdx.x & 15) << 6;    // 0,64,...,960
    const int u   = u0 + tid;

    const float sv = smoothing_var[u];
    const float s  = 1.0f / (1.0f + expf(-sv));
    const float c  = 1.0f - s;
    float level    = level_var[u];

    const float* __restrict__ xb = x   + (size_t)b * LP_T * LP_U;
    float*       __restrict__ ob = out + (size_t)b * LP_T * LP_U;

    // Load mapping: row = 64 floats = 256B = 16 threads x 16B.
    // 64 threads cover 4 rows per step; 16 steps cover the 64-row tile.
    const int lrow = tid >> 4;          // 0..3
    const int lcol = (tid & 15) << 2;   // 0,4,...,60  (float index in row)

    // Prologue: tiles 0..3 in flight (4 groups)
#pragma unroll
    for (int p = 0; p < 4; p++) {
        float* st = xs + p * STAGE_FLOATS;
#pragma unroll
        for (int k = 0; k < 16; k++) {
            const int r = lrow + 4 * k;
            cp_async16(st + r * TPB + lcol,
                       xb + (size_t)(p * TT + r) * LP_U + u0 + lcol);
        }
        cp_async_commit();
    }

    for (int it = 0; it < NIT; it++) {
        cp_async_wait<3>();     // <=3 of 4 pending -> tile 'it' has landed
        __syncthreads();        // all slices visible; slot (it+4)%RING free

        // Issue tile it+4 (its slot held tile it-2, consumed & fenced).
        const int ls = it + 4;
        if (ls < NIT) {
            float* st = xs + (ls % RING) * STAGE_FLOATS;
#pragma unroll
            for (int k = 0; k < 16; k++) {
                const int r = lrow + 4 * k;
                cp_async16(st + r * TPB + lcol,
                           xb + (size_t)(ls * TT + r) * LP_U + u0 + lcol);
            }
        }
        cp_async_commit();      // empty groups near the end keep counts uniform

        // Consume tile it: serial carry, coalesced stores
        const float* tile = xs + (it % RING) * STAGE_FLOATS;
        float* op = ob + (size_t)(it * TT) * LP_U + u;
#pragma unroll
        for (int t = 0; t < TT; t++) {
            level = fmaf(s, level, c * tile[t * TPB + tid]);
            __stcs(op + (size_t)t * LP_U, level);
        }
    }
}

extern "C" void kernel_launch(void* const* d_in, const int* in_sizes, int n_in,
                              void* d_out, int out_size)
{
    const float* x         = (const float*)d_in[0];  // [B,T,U]
    const float* level_var = (const float*)d_in[1];  // [1,U]
    const float* smoothing = (const float*)d_in[2];  // [1,U]
    float* out             = (float*)d_out;          // [B,T,U]

    static int smem_set = 0;
    if (!smem_set) {
        cudaFuncSetAttribute(lowpass_cpasync_kernel,
                             cudaFuncAttributeMaxDynamicSharedMemorySize,
                             SMEM_BYTES);
        smem_set = 1;
    }

    const int blocks = LP_B * (LP_U / TPB);          // 256
    lowpass_cpasync_kernel<<<blocks, TPB, SMEM_BYTES>>>(x, level_var, smoothing, out);
}

// round 11
// speedup vs baseline: 1.0240x; 1.0240x over previous
#include <cuda_runtime.h>
#include <cuda_bf16.h>
#include <math.h>

// Lowpass EMA scan: out[b,t,u] = (1-s[u])*x[b,t,u] + s[u]*prev
// Thread-per-chain (carry in register) + cp.async-staged input tiles.
// R11: R10's finer pipeline quantum WITHOUT the L2 cache-hint PTX that
// trapped (illegal instruction). Plain cp.async.cg as in R7/R8.
//  - TT=32 (16KB tiles), RING=12, AHEAD=8 tiles (128KB/SM) in flight,
//    wait<7> -> half the stall quantum per straggling tile vs TT=64.
// Geometry: 128 blocks x 128 threads (best known).

#define LP_B   16
#define LP_T   2048
#define LP_U   1024
#define TPB    128           // threads = chains per block
#define TT     32            // t per tile
#define NIT    (LP_T / TT)   // 64
#define RING   12
#define AHEAD  8             // tiles in flight
#define STAGE_FLOATS (TT * TPB)                 // 4096 floats = 16KB
#define SMEM_BYTES   (RING * STAGE_FLOATS * 4)  // 192KB

__device__ __forceinline__ void cp_async16(float* smem_dst, const float* gsrc) {
    unsigned sdst = (unsigned)__cvta_generic_to_shared(smem_dst);
    asm volatile("cp.async.cg.shared.global [%0], [%1], 16;\n"
                 :: "r"(sdst), "l"(gsrc));
}
__device__ __forceinline__ void cp_async_commit() {
    asm volatile("cp.async.commit_group;\n" ::: "memory");
}
template <int N>
__device__ __forceinline__ void cp_async_wait() {
    asm volatile("cp.async.wait_group %0;\n" :: "n"(N) : "memory");
}

__global__ void __launch_bounds__(TPB, 1)
lowpass_cpasync_kernel(const float* __restrict__ x,
                       const float* __restrict__ level_var,
                       const float* __restrict__ smoothing_var,
                       float* __restrict__ out)
{
    extern __shared__ float xs[];   // [RING][TT][TPB]

    const int tid = threadIdx.x;
    const int b   = blockIdx.x >> 3;          // 0..15
    const int u0  = (blockIdx.x & 7) << 7;    // 0,128,...,896
    const int u   = u0 + tid;

    const float sv = smoothing_var[u];
    const float s  = 1.0f / (1.0f + expf(-sv));
    const float c  = 1.0f - s;
    float level    = level_var[u];

    const float* __restrict__ xb = x   + (size_t)b * LP_T * LP_U;
    float*       __restrict__ ob = out + (size_t)b * LP_T * LP_U;

    // Load mapping: row = 128 floats = 512B = 32 threads x 16B.
    // 128 threads cover 4 rows per step; 8 steps cover a 32-row tile.
    const int lrow = tid >> 5;          // 0..3
    const int lcol = (tid & 31) << 2;   // 0,4,...,124

    // Prologue: tiles 0..AHEAD-1 in flight
#pragma unroll
    for (int p = 0; p < AHEAD; p++) {
        float* st = xs + p * STAGE_FLOATS;
#pragma unroll
        for (int k = 0; k < 8; k++) {
            const int r = lrow + 4 * k;
            cp_async16(st + r * TPB + lcol,
                       xb + (size_t)(p * TT + r) * LP_U + u0 + lcol);
        }
        cp_async_commit();
    }

    for (int it = 0; it < NIT; it++) {
        cp_async_wait<AHEAD - 1>();  // tile 'it' has landed
        __syncthreads();             // all slices visible; old slot free

        // Issue tile it+AHEAD (slot held tile it-4: consumed, fenced at it-3)
        const int ls = it + AHEAD;
        if (ls < NIT) {
            float* st = xs + (ls % RING) * STAGE_FLOATS;
#pragma unroll
            for (int k = 0; k < 8; k++) {
                const int r = lrow + 4 * k;
                cp_async16(st + r * TPB + lcol,
                           xb + (size_t)(ls * TT + r) * LP_U + u0 + lcol);
            }
        }
        cp_async_commit();           // empty groups keep counts uniform

        // Consume tile it: serial carry, coalesced streaming stores
        const float* tile = xs + (it % RING) * STAGE_FLOATS;
        float* op = ob + (size_t)(it * TT) * LP_U + u;
#pragma unroll
        for (int t = 0; t < TT; t++) {
            level = fmaf(s, level, c * tile[t * TPB + tid]);
            __stcs(op + (size_t)t * LP_U, level);
        }
    }
}

extern "C" void kernel_launch(void* const* d_in, const int* in_sizes, int n_in,
                              void* d_out, int out_size)
{
    const float* x         = (const float*)d_in[0];  // [B,T,U]
    const float* level_var = (const float*)d_in[1];  // [1,U]
    const float* smoothing = (const float*)d_in[2];  // [1,U]
    float* out             = (float*)d_out;          // [B,T,U]

    static int smem_set = 0;
    if (!smem_set) {
        cudaFuncSetAttribute(lowpass_cpasync_kernel,
                             cudaFuncAttributeMaxDynamicSharedMemorySize,
                             SMEM_BYTES);
        smem_set = 1;
    }

    const int blocks = LP_B * (LP_U / TPB);          // 128
    lowpass_cpasync_kernel<<<blocks, TPB, SMEM_BYTES>>>(x, level_var, smoothing, out);
}